// round 1
// baseline (speedup 1.0000x reference)
#include <cuda_runtime.h>
#include <cuda_bf16.h>

// Problem constants (fixed by the problem spec)
#define NS        4096
#define NQ_TOTAL  32768     // B * N_Q = 4 * 8192
#define NQ_PER_B  8192
#define KNN       8
#define FDIM      256
#define FDIM4     (FDIM/4)

// Inter-kernel scratch (device globals: allowed; no allocation)
__device__ float g_w  [NQ_TOTAL * KNN];
__device__ int   g_idx[NQ_TOTAL * KNN];

// ---------------------------------------------------------------------------
// Kernel 1: brute-force KNN (top-8 by score t = q.s - 0.5*|s|^2, max == nearest)
// One thread per query. Sensors staged in shared memory as float4 (x,y,z,half_s2).
// All lanes of a warp read the same sensor each iteration -> broadcast LDS.128.
// ---------------------------------------------------------------------------
__global__ void __launch_bounds__(256) knn_kernel(const float* __restrict__ qc,
                                                  const float* __restrict__ sc)
{
    extern __shared__ float4 sh[];   // NS * 16B = 64 KB
    const int tid = threadIdx.x;

    // Stage + preprocess sensor coords
    for (int i = tid; i < NS; i += 256) {
        float sx = sc[3*i+0], sy = sc[3*i+1], sz = sc[3*i+2];
        sh[i] = make_float4(sx, sy, sz, 0.5f * (sx*sx + sy*sy + sz*sz));
    }
    __syncthreads();

    const int q = blockIdx.x * 256 + tid;   // grid sized exactly: no bounds check
    const float qx = qc[3*q+0];
    const float qy = qc[3*q+1];
    const float qz = qc[3*q+2];

    // Descending score list: tv[0] = best (largest t / nearest), tv[7] = worst kept
    float tv[KNN];
    int   ti[KNN];
#pragma unroll
    for (int j = 0; j < KNN; j++) { tv[j] = -3.0e38f; ti[j] = 0; }

#pragma unroll 4
    for (int s = 0; s < NS; s++) {
        float4 h = sh[s];
        float  t = fmaf(qx, h.x, fmaf(qy, h.y, fmaf(qz, h.z, -h.w)));
        if (t > tv[KNN-1]) {
            tv[KNN-1] = t; ti[KNN-1] = s;
            // single bubble pass restores descending order (only last slot changed)
#pragma unroll
            for (int j = KNN-1; j > 0; j--) {
                if (tv[j] > tv[j-1]) {
                    float ft = tv[j]; tv[j] = tv[j-1]; tv[j-1] = ft;
                    int   it = ti[j]; ti[j] = ti[j-1]; ti[j-1] = it;
                }
            }
        }
    }

    // Recompute exact distances for the 8 winners (no cancellation), IDW weights
    float w[KNN];
    float wsum = 0.0f;
#pragma unroll
    for (int j = 0; j < KNN; j++) {
        float4 h  = sh[ti[j]];
        float dx = qx - h.x, dy = qy - h.y, dz = qz - h.z;
        float d2 = fmaf(dx, dx, fmaf(dy, dy, dz*dz));
        float d  = sqrtf(d2);
        float wj = 1.0f / (d + 1e-8f);
        w[j] = wj;
        wsum += wj;
    }
    const float inv = 1.0f / wsum;
#pragma unroll
    for (int j = 0; j < KNN; j++) {
        g_w  [q*KNN + j] = w[j] * inv;
        g_idx[q*KNN + j] = ti[j];
    }
}

// ---------------------------------------------------------------------------
// Kernel 2: weighted feature gather. One warp per query, coalesced float4 rows.
// Each lane accumulates 2 float4 (= 8 floats) of the 256-wide feature vector.
// ---------------------------------------------------------------------------
__global__ void __launch_bounds__(256) gather_kernel(const float* __restrict__ feats,
                                                     float* __restrict__ out)
{
    const int gw   = (blockIdx.x * 256 + threadIdx.x) >> 5;  // global query id
    const int lane = threadIdx.x & 31;
    const int b    = gw >> 13;                               // / NQ_PER_B

    const float4* __restrict__ fb =
        reinterpret_cast<const float4*>(feats) + (size_t)b * NS * FDIM4;

    float4 a0 = make_float4(0.f, 0.f, 0.f, 0.f);
    float4 a1 = make_float4(0.f, 0.f, 0.f, 0.f);

#pragma unroll
    for (int k = 0; k < KNN; k++) {
        const float wk = g_w  [gw*KNN + k];   // same addr across warp -> broadcast
        const int   id = g_idx[gw*KNN + k];
        const float4* __restrict__ fr = fb + (size_t)id * FDIM4;
        float4 f0 = fr[lane];
        float4 f1 = fr[lane + 32];
        a0.x = fmaf(wk, f0.x, a0.x); a0.y = fmaf(wk, f0.y, a0.y);
        a0.z = fmaf(wk, f0.z, a0.z); a0.w = fmaf(wk, f0.w, a0.w);
        a1.x = fmaf(wk, f1.x, a1.x); a1.y = fmaf(wk, f1.y, a1.y);
        a1.z = fmaf(wk, f1.z, a1.z); a1.w = fmaf(wk, f1.w, a1.w);
    }

    float4* __restrict__ o = reinterpret_cast<float4*>(out) + (size_t)gw * FDIM4;
    o[lane]      = a0;
    o[lane + 32] = a1;
}

// ---------------------------------------------------------------------------
// Launch: two dependent kernels, graph-capturable, allocation-free.
// ---------------------------------------------------------------------------
extern "C" void kernel_launch(void* const* d_in, const int* in_sizes, int n_in,
                              void* d_out, int out_size)
{
    const float* qc = (const float*)d_in[0];   // query_coords   (B, NQ, 3)
    const float* sc = (const float*)d_in[1];   // sensor_coords  (NS, 3)
    const float* ft = (const float*)d_in[2];   // sensor_features(B, NS, F)

    // Opt in to 64 KB dynamic smem (non-stream API; capture-safe, idempotent)
    cudaFuncSetAttribute(knn_kernel,
                         cudaFuncAttributeMaxDynamicSharedMemorySize, NS * 16);

    knn_kernel<<<NQ_TOTAL / 256, 256, NS * 16>>>(qc, sc);
    gather_kernel<<<(NQ_TOTAL * 32) / 256, 256>>>(ft, (float*)d_out);
}